// round 1
// baseline (speedup 1.0000x reference)
#include <cuda_runtime.h>
#include <math.h>
#include <stdint.h>

#define N_NODES 50000
#define N_EDGES 800000
#define D_IN    256
#define QKVS_W  1024
#define SC_CAP  256

// ---------------- scratch (device globals; no allocation allowed) ----------------
__device__ float g_Wcat[D_IN * QKVS_W];                 // packed [256,1024] weights
__device__ float g_bcat[QKVS_W];
__device__ float g_qkvs[(size_t)N_NODES * QKVS_W];      // Q|K|V|Skip per node
__device__ float g_multi[(size_t)N_NODES * 256];        // concat-head attention output
__device__ float g_tmp[(size_t)N_NODES * 256];          // pre-LN output GEMM result
__device__ int   g_deg[N_NODES];
__device__ int   g_off[N_NODES];
__device__ int   g_cur[N_NODES];
__device__ int   g_srcs[N_EDGES];                       // edge srcs sorted by dst

// ---------------- prep: pack weights/bias, zero counters ----------------
__global__ void prep_kernel(const float* __restrict__ Wq, const float* __restrict__ Wk,
                            const float* __restrict__ Wv, const float* __restrict__ Ws,
                            const float* __restrict__ bq, const float* __restrict__ bk,
                            const float* __restrict__ bv, const float* __restrict__ bs)
{
    int idx = blockIdx.x * blockDim.x + threadIdx.x;
    if (idx < D_IN * QKVS_W) {
        int d  = idx >> 10;          // 0..255
        int o  = idx & 1023;         // 0..1023
        int sec = o >> 8;            // 0..3 : Q,K,V,Skip
        int oo  = o & 255;           // h*64 + kk
        int h   = oo >> 6;
        int kk  = oo & 63;
        const float* W = (sec == 0) ? Wq : (sec == 1) ? Wk : (sec == 2) ? Wv : Ws;
        // W is [H][256][64]
        g_Wcat[idx] = W[((h << 8) + d) * 64 + kk];
    }
    if (idx < QKVS_W) {
        int sec = idx >> 8, oo = idx & 255;
        const float* b = (sec == 0) ? bq : (sec == 1) ? bk : (sec == 2) ? bv : bs;
        g_bcat[idx] = b[oo];
    }
    if (idx < N_NODES) {
        g_deg[idx] = 0;
        g_cur[idx] = 0;
    }
}

// ---------------- SGEMM: C[M,Nc] = A[M,K] * B[K,Nc] + bias ----------------
// 128x64 tile, BK=16, 256 threads, 8x4 per thread
__global__ __launch_bounds__(256) void sgemm_bias(
    const float* __restrict__ A, const float* __restrict__ B,
    const float* __restrict__ bias, float* __restrict__ C,
    int M, int K, int Nc)
{
    __shared__ float As[16][128];
    __shared__ float Bs[16][64];

    int tid = threadIdx.x;
    int tx = tid & 15;            // 0..15 -> 4 cols
    int ty = tid >> 4;            // 0..15 -> 8 rows
    int row0 = blockIdx.y * 128;
    int col0 = blockIdx.x * 64;

    float acc[8][4];
#pragma unroll
    for (int i = 0; i < 8; i++)
#pragma unroll
        for (int j = 0; j < 4; j++) acc[i][j] = 0.f;

    int am = tid >> 1;            // 0..127
    int ak = (tid & 1) * 8;       // 0 or 8
    int bk = tid >> 4;            // 0..15
    int bc = (tid & 15) * 4;      // 0..60

    for (int k0 = 0; k0 < K; k0 += 16) {
        float4 a0 = make_float4(0.f, 0.f, 0.f, 0.f);
        float4 a1 = make_float4(0.f, 0.f, 0.f, 0.f);
        int ar = row0 + am;
        if (ar < M) {
            const float* ap = A + (size_t)ar * K + k0 + ak;
            a0 = *(const float4*)ap;
            a1 = *(const float4*)(ap + 4);
        }
        As[ak + 0][am] = a0.x; As[ak + 1][am] = a0.y;
        As[ak + 2][am] = a0.z; As[ak + 3][am] = a0.w;
        As[ak + 4][am] = a1.x; As[ak + 5][am] = a1.y;
        As[ak + 6][am] = a1.z; As[ak + 7][am] = a1.w;

        *(float4*)&Bs[bk][bc] = *(const float4*)&B[(size_t)(k0 + bk) * Nc + col0 + bc];

        __syncthreads();

#pragma unroll
        for (int k = 0; k < 16; k++) {
            float4 av0 = *(const float4*)&As[k][ty * 8];
            float4 av1 = *(const float4*)&As[k][ty * 8 + 4];
            float4 bv  = *(const float4*)&Bs[k][tx * 4];
            float ar8[8] = {av0.x, av0.y, av0.z, av0.w, av1.x, av1.y, av1.z, av1.w};
            float br4[4] = {bv.x, bv.y, bv.z, bv.w};
#pragma unroll
            for (int i = 0; i < 8; i++)
#pragma unroll
                for (int j = 0; j < 4; j++)
                    acc[i][j] += ar8[i] * br4[j];
        }
        __syncthreads();
    }

    float4 b4 = *(const float4*)&bias[col0 + tx * 4];
#pragma unroll
    for (int i = 0; i < 8; i++) {
        int r = row0 + ty * 8 + i;
        if (r < M) {
            float4 o;
            o.x = acc[i][0] + b4.x;
            o.y = acc[i][1] + b4.y;
            o.z = acc[i][2] + b4.z;
            o.w = acc[i][3] + b4.w;
            *(float4*)&C[(size_t)r * Nc + col0 + tx * 4] = o;
        }
    }
}

// ---------------- CSR build ----------------
__global__ void hist_kernel(const int* __restrict__ dst, int E)
{
    int e = blockIdx.x * blockDim.x + threadIdx.x;
    if (e < E) atomicAdd(&g_deg[dst[e]], 1);
}

__global__ void scan_kernel(int n)
{
    __shared__ int sh[1024];
    __shared__ int carry;
    int tid = threadIdx.x;
    if (tid == 0) carry = 0;
    __syncthreads();
    for (int base = 0; base < n; base += 1024) {
        int i = base + tid;
        int v = (i < n) ? g_deg[i] : 0;
        sh[tid] = v;
        __syncthreads();
#pragma unroll
        for (int off = 1; off < 1024; off <<= 1) {
            int t = (tid >= off) ? sh[tid - off] : 0;
            __syncthreads();
            sh[tid] += t;
            __syncthreads();
        }
        int total = sh[1023];
        if (i < n) g_off[i] = carry + sh[tid] - v;  // exclusive
        __syncthreads();
        if (tid == 0) carry += total;
        __syncthreads();
    }
}

__global__ void scatter_kernel(const int* __restrict__ src, const int* __restrict__ dst, int E)
{
    int e = blockIdx.x * blockDim.x + threadIdx.x;
    if (e < E) {
        int d = dst[e];
        int pos = g_off[d] + atomicAdd(&g_cur[d], 1);
        g_srcs[pos] = src[e];
    }
}

// ---------------- attention: one block per node, one warp per head ----------------
__global__ __launch_bounds__(128) void attn_kernel(int n_nodes)
{
    int n = blockIdx.x;
    if (n >= n_nodes) return;
    int h    = threadIdx.x >> 5;   // head = warp id
    int lane = threadIdx.x & 31;

    __shared__ float sc[4][SC_CAP];

    int deg = g_deg[n];
    int off = g_off[n];

    const float* qrow = g_qkvs + (size_t)n * QKVS_W + h * 64;
    float q0 = qrow[lane];
    float q1 = qrow[lane + 32];

    // pass 1: scores + max
    float m = -INFINITY;
    for (int j = 0; j < deg; j++) {
        int src = g_srcs[off + j];
        const float* kr = g_qkvs + (size_t)src * QKVS_W + 256 + h * 64;
        float p = q0 * kr[lane] + q1 * kr[lane + 32];
#pragma unroll
        for (int o = 16; o; o >>= 1) p += __shfl_xor_sync(0xffffffffu, p, o);
        p *= 0.125f;   // 1/sqrt(64)
        if (lane == 0 && j < SC_CAP) sc[h][j] = p;
        m = fmaxf(m, p);
    }
    __syncwarp();

    // pass 2: exp-sum + weighted V accumulation (normalize at end)
    float s = 0.f, a0 = 0.f, a1 = 0.f;
    for (int j = 0; j < deg; j++) {
        int src = g_srcs[off + j];
        float p;
        if (j < SC_CAP) {
            p = sc[h][j];
        } else {
            const float* kr = g_qkvs + (size_t)src * QKVS_W + 256 + h * 64;
            float pp = q0 * kr[lane] + q1 * kr[lane + 32];
#pragma unroll
            for (int o = 16; o; o >>= 1) pp += __shfl_xor_sync(0xffffffffu, pp, o);
            p = pp * 0.125f;
        }
        float e = expf(p - m);
        const float* vr = g_qkvs + (size_t)src * QKVS_W + 512 + h * 64;
        a0 += e * vr[lane];
        a1 += e * vr[lane + 32];
        s += e;
    }

    float inv = 1.f / (s + 1e-16f);
    const float* sr = g_qkvs + (size_t)n * QKVS_W + 768 + h * 64;
    float* outp = g_multi + (size_t)n * 256 + h * 64;
    outp[lane]      = a0 * inv + sr[lane];
    outp[lane + 32] = a1 * inv + sr[lane + 32];
}

// ---------------- residual + LayerNorm: one warp per row ----------------
__global__ __launch_bounds__(256) void ln_kernel(const float* __restrict__ x,
                                                 const float* __restrict__ gamma,
                                                 const float* __restrict__ beta,
                                                 float* __restrict__ out, int n_nodes)
{
    int row  = blockIdx.x * 8 + (threadIdx.x >> 5);
    int lane = threadIdx.x & 31;
    if (row >= n_nodes) return;

    const float* t  = g_tmp + (size_t)row * 256;
    const float* xr = x + (size_t)row * 256;

    float h[8];
    float s = 0.f, s2 = 0.f;
#pragma unroll
    for (int i = 0; i < 8; i++) {
        int c = lane + 32 * i;
        h[i] = t[c] + xr[c];
        s  += h[i];
        s2 += h[i] * h[i];
    }
#pragma unroll
    for (int o = 16; o; o >>= 1) {
        s  += __shfl_xor_sync(0xffffffffu, s,  o);
        s2 += __shfl_xor_sync(0xffffffffu, s2, o);
    }
    float mu  = s * (1.f / 256.f);
    float var = s2 * (1.f / 256.f) - mu * mu;
    float r   = rsqrtf(var + 1e-5f);
#pragma unroll
    for (int i = 0; i < 8; i++) {
        int c = lane + 32 * i;
        out[(size_t)row * 256 + c] = (h[i] - mu) * r * gamma[c] + beta[c];
    }
}

// ---------------- launch ----------------
extern "C" void kernel_launch(void* const* d_in, const int* in_sizes, int n_in,
                              void* d_out, int out_size)
{
    const float* x     = (const float*)d_in[0];
    const int*   ei    = (const int*)d_in[1];
    const float* Wq    = (const float*)d_in[2];
    const float* bq    = (const float*)d_in[3];
    const float* Wk    = (const float*)d_in[4];
    const float* bk    = (const float*)d_in[5];
    const float* Wv    = (const float*)d_in[6];
    const float* bv    = (const float*)d_in[7];
    const float* Wsk   = (const float*)d_in[8];
    const float* bsk   = (const float*)d_in[9];
    const float* Wout  = (const float*)d_in[10];
    const float* bout  = (const float*)d_in[11];
    const float* ln_g  = (const float*)d_in[12];
    const float* ln_b  = (const float*)d_in[13];
    float* out = (float*)d_out;

    int N = in_sizes[0] / D_IN;     // 50000
    int E = in_sizes[1] / 2;        // 800000

    void* p;
    cudaGetSymbolAddress(&p, g_Wcat);  float* Wcat  = (float*)p;
    cudaGetSymbolAddress(&p, g_bcat);  float* bcat  = (float*)p;
    cudaGetSymbolAddress(&p, g_qkvs);  float* qkvs  = (float*)p;
    cudaGetSymbolAddress(&p, g_multi); float* multi = (float*)p;
    cudaGetSymbolAddress(&p, g_tmp);   float* tmp   = (float*)p;

    const int* srcs = ei;
    const int* dsts = ei + E;

    // 1. pack weights + zero counters
    prep_kernel<<<(D_IN * QKVS_W + 255) / 256, 256>>>(Wq, Wk, Wv, Wsk, bq, bk, bv, bsk);

    // 2. QKVS projection GEMM: [N,256] x [256,1024]
    {
        dim3 grid(QKVS_W / 64, (N + 127) / 128);
        sgemm_bias<<<grid, 256>>>(x, Wcat, bcat, qkvs, N, D_IN, QKVS_W);
    }

    // 3. CSR build by destination
    hist_kernel<<<(E + 255) / 256, 256>>>(dsts, E);
    scan_kernel<<<1, 1024>>>(N);
    scatter_kernel<<<(E + 255) / 256, 256>>>(srcs, dsts, E);

    // 4. per-node softmax attention + skip
    attn_kernel<<<N, 128>>>(N);

    // 5. output GEMM: [N,256] x [256,256]
    {
        dim3 grid(256 / 64, (N + 127) / 128);
        sgemm_bias<<<grid, 256>>>(multi, Wout, bout, tmp, N, 256, 256);
    }

    // 6. residual + LayerNorm
    ln_kernel<<<(N + 7) / 8, 256>>>(x, ln_g, ln_b, out, N);
}

// round 3
// speedup vs baseline: 1.5827x; 1.5827x over previous
#include <cuda_runtime.h>
#include <cuda_bf16.h>
#include <math.h>
#include <stdint.h>

#define N_NODES 50000
#define N_EDGES 800000
#define D_IN    256
#define QKVS_W  1024
#define KAUG    768
#define SC_CAP  256

typedef __nv_bfloat16 bf16;

// ---------------- scratch (device globals) ----------------
__device__ bf16  g_Waug1[KAUG * QKVS_W];               // augmented QKVS weights [768,1024]
__device__ bf16  g_Waug2[KAUG * 256];                  // augmented Wout [768,256]
__device__ float g_bcat[QKVS_W];
__device__ bf16  g_xaug[(size_t)N_NODES * KAUG];       // augmented x [N,768] = [hi|lo|hi]
__device__ float g_qkvs[(size_t)N_NODES * QKVS_W];     // Q|K|V|Skip per node (fp32)
__device__ bf16  g_maug[(size_t)N_NODES * KAUG];       // augmented attention output
__device__ float g_tmp[(size_t)N_NODES * 256];         // pre-LN output GEMM result
__device__ int   g_deg[N_NODES];
__device__ int   g_off[N_NODES];
__device__ int   g_cur[N_NODES];
__device__ int   g_srcs[N_EDGES];

__device__ __forceinline__ void split_bf16(float v, bf16& hi, bf16& lo) {
    hi = __float2bfloat16(v);
    lo = __float2bfloat16(v - __bfloat162float(hi));
}

// ---------------- prep: pack augmented weights, zero counters ----------------
__global__ void prep_w_kernel(const float* __restrict__ Wq, const float* __restrict__ Wk,
                              const float* __restrict__ Wv, const float* __restrict__ Ws,
                              const float* __restrict__ bq, const float* __restrict__ bk,
                              const float* __restrict__ bv, const float* __restrict__ bs,
                              const float* __restrict__ Wout)
{
    int idx = blockIdx.x * blockDim.x + threadIdx.x;
    if (idx < D_IN * QKVS_W) {
        int d  = idx >> 10;          // 0..255 (input dim)
        int o  = idx & 1023;         // 0..1023 (output col)
        int sec = o >> 8;
        int oo  = o & 255;
        int h   = oo >> 6;
        int kk  = oo & 63;
        const float* W = (sec == 0) ? Wq : (sec == 1) ? Wk : (sec == 2) ? Wv : Ws;
        float w = W[((h << 8) + d) * 64 + kk];
        bf16 hi, lo; split_bf16(w, hi, lo);
        g_Waug1[(size_t)d * QKVS_W + o] = hi;          // rows [0,256): hi
        g_Waug1[(size_t)(d + 256) * QKVS_W + o] = hi;  // rows [256,512): hi (pairs with A-lo)
        g_Waug1[(size_t)(d + 512) * QKVS_W + o] = lo;  // rows [512,768): lo (pairs with A-hi)
    }
    if (idx < 256 * 256) {
        int d = idx >> 8, o = idx & 255;
        float w = Wout[d * 256 + o];
        bf16 hi, lo; split_bf16(w, hi, lo);
        g_Waug2[(size_t)d * 256 + o] = hi;
        g_Waug2[(size_t)(d + 256) * 256 + o] = hi;
        g_Waug2[(size_t)(d + 512) * 256 + o] = lo;
    }
    if (idx < QKVS_W) {
        int sec = idx >> 8, oo = idx & 255;
        const float* b = (sec == 0) ? bq : (sec == 1) ? bk : (sec == 2) ? bv : bs;
        g_bcat[idx] = b[oo];
    }
    if (idx < N_NODES) { g_deg[idx] = 0; g_cur[idx] = 0; }
}

// x [N,256] fp32 -> xaug [N,768] bf16 ([hi|lo|hi])
__global__ void conv_x_kernel(const float* __restrict__ x, int n_nodes)
{
    int idx = blockIdx.x * blockDim.x + threadIdx.x;   // over N*128 float2s
    if (idx >= n_nodes * 128) return;
    int n = idx >> 7;
    int c = (idx & 127) * 2;
    float2 v = *(const float2*)&x[(size_t)n * 256 + c];
    bf16 h0, l0, h1, l1;
    split_bf16(v.x, h0, l0);
    split_bf16(v.y, h1, l1);
    __nv_bfloat162 hp; hp.x = h0; hp.y = h1;
    __nv_bfloat162 lp; lp.x = l0; lp.y = l1;
    bf16* base = g_xaug + (size_t)n * KAUG;
    *(__nv_bfloat162*)(base + c)       = hp;
    *(__nv_bfloat162*)(base + 256 + c) = lp;
    *(__nv_bfloat162*)(base + 512 + c) = hp;
}

// ---------------- tensor-core GEMM: C[M,Nc] = Aaug[M,768] * Baug[768,Nc] + bias --------
// 128x128 tile, BK=32, 256 threads (8 warps 2x4), m16n8k16 bf16 mma, cp.async double buffer
#define ASTRIDE 40
#define BSTRIDE 136

__device__ __forceinline__ void cp16(uint32_t s, const void* g) {
    asm volatile("cp.async.cg.shared.global [%0], [%1], 16;\n" :: "r"(s), "l"(g));
}
__device__ __forceinline__ uint32_t s2u(const void* p) {
    return (uint32_t)__cvta_generic_to_shared(p);
}

__global__ __launch_bounds__(256) void mma_gemm(
    const bf16* __restrict__ A, const bf16* __restrict__ B,
    const float* __restrict__ bias, float* __restrict__ C,
    int M, int Nc)
{
    __shared__ bf16 As[2][128][ASTRIDE];
    __shared__ bf16 Bs[2][32][BSTRIDE];

    int tid  = threadIdx.x;
    int warp = tid >> 5, lane = tid & 31;
    int wm = (warp >> 2) * 64;       // warp m-offset within block tile
    int wn = (warp & 3) * 32;        // warp n-offset
    int row0 = blockIdx.y * 128;
    int col0 = blockIdx.x * 128;

    float acc[4][4][4];
#pragma unroll
    for (int i = 0; i < 4; i++)
#pragma unroll
        for (int j = 0; j < 4; j++)
#pragma unroll
            for (int k = 0; k < 4; k++) acc[i][j][k] = 0.f;

    // loader indices
    int ar = tid >> 2, aq = tid & 3;           // A: 2 rows per thread (ar, ar+64), 16B chunk aq
    int br = tid >> 4, bq = tid & 15;          // B: 2 rows per thread (br, br+16), chunk bq

    const int NT = KAUG / 32;   // 24

    // prologue: load tile 0
    {
        int k0 = 0, buf = 0;
        int g0 = min(row0 + ar, M - 1), g1 = min(row0 + 64 + ar, M - 1);
        cp16(s2u(&As[buf][ar][aq * 8]),      A + (size_t)g0 * KAUG + k0 + aq * 8);
        cp16(s2u(&As[buf][64 + ar][aq * 8]), A + (size_t)g1 * KAUG + k0 + aq * 8);
        cp16(s2u(&Bs[buf][br][bq * 8]),      B + (size_t)(k0 + br) * Nc + col0 + bq * 8);
        cp16(s2u(&Bs[buf][16 + br][bq * 8]), B + (size_t)(k0 + 16 + br) * Nc + col0 + bq * 8);
        asm volatile("cp.async.commit_group;\n");
    }

    for (int t = 0; t < NT; t++) {
        int buf = t & 1;
        if (t + 1 < NT) {
            int k0 = (t + 1) * 32, nb = (t + 1) & 1;
            int g0 = min(row0 + ar, M - 1), g1 = min(row0 + 64 + ar, M - 1);
            cp16(s2u(&As[nb][ar][aq * 8]),      A + (size_t)g0 * KAUG + k0 + aq * 8);
            cp16(s2u(&As[nb][64 + ar][aq * 8]), A + (size_t)g1 * KAUG + k0 + aq * 8);
            cp16(s2u(&Bs[nb][br][bq * 8]),      B + (size_t)(k0 + br) * Nc + col0 + bq * 8);
            cp16(s2u(&Bs[nb][16 + br][bq * 8]), B + (size_t)(k0 + 16 + br) * Nc + col0 + bq * 8);
            asm volatile("cp.async.commit_group;\n");
            asm volatile("cp.async.wait_group 1;\n");
        } else {
            asm volatile("cp.async.wait_group 0;\n");
        }
        __syncthreads();

#pragma unroll
        for (int kk = 0; kk < 32; kk += 16) {
            uint32_t af[4][4];
#pragma unroll
            for (int mt = 0; mt < 4; mt++) {
                uint32_t addr = s2u(&As[buf][wm + mt * 16 + (lane & 15)][kk + (lane >> 4) * 8]);
                asm volatile("ldmatrix.sync.aligned.m8n8.x4.shared.b16 {%0,%1,%2,%3}, [%4];"
                             : "=r"(af[mt][0]), "=r"(af[mt][1]), "=r"(af[mt][2]), "=r"(af[mt][3])
                             : "r"(addr));
            }
            uint32_t bfr[4][2];
#pragma unroll
            for (int nt = 0; nt < 4; nt++) {
                uint32_t addr = s2u(&Bs[buf][kk + (lane & 15)][wn + nt * 8]);
                asm volatile("ldmatrix.sync.aligned.m8n8.x2.trans.shared.b16 {%0,%1}, [%2];"
                             : "=r"(bfr[nt][0]), "=r"(bfr[nt][1]) : "r"(addr));
            }
#pragma unroll
            for (int mt = 0; mt < 4; mt++)
#pragma unroll
                for (int nt = 0; nt < 4; nt++) {
                    asm volatile(
                        "mma.sync.aligned.m16n8k16.row.col.f32.bf16.bf16.f32 "
                        "{%0,%1,%2,%3}, {%4,%5,%6,%7}, {%8,%9}, {%0,%1,%2,%3};"
                        : "+f"(acc[mt][nt][0]), "+f"(acc[mt][nt][1]),
                          "+f"(acc[mt][nt][2]), "+f"(acc[mt][nt][3])
                        : "r"(af[mt][0]), "r"(af[mt][1]), "r"(af[mt][2]), "r"(af[mt][3]),
                          "r"(bfr[nt][0]), "r"(bfr[nt][1]));
                }
        }
        __syncthreads();
    }

    // epilogue: + bias, store
#pragma unroll
    for (int mt = 0; mt < 4; mt++) {
#pragma unroll
        for (int nt = 0; nt < 4; nt++) {
            int c = col0 + wn + nt * 8 + 2 * (lane & 3);
            float2 b2 = *(const float2*)&bias[c];
            int r0 = row0 + wm + mt * 16 + (lane >> 2);
            if (r0 < M) {
                float2 o; o.x = acc[mt][nt][0] + b2.x; o.y = acc[mt][nt][1] + b2.y;
                *(float2*)&C[(size_t)r0 * Nc + c] = o;
            }
            int r1 = r0 + 8;
            if (r1 < M) {
                float2 o; o.x = acc[mt][nt][2] + b2.x; o.y = acc[mt][nt][3] + b2.y;
                *(float2*)&C[(size_t)r1 * Nc + c] = o;
            }
        }
    }
}

// ---------------- CSR build ----------------
__global__ void hist_kernel(const int* __restrict__ dst, int E)
{
    int e = blockIdx.x * blockDim.x + threadIdx.x;
    if (e < E) atomicAdd(&g_deg[dst[e]], 1);
}

__global__ void scan_kernel(int n)
{
    __shared__ int warp_sums[32];
    int tid = threadIdx.x;                 // 0..1023
    int ch  = (n + 1023) / 1024;
    int begin = tid * ch, end = min(begin + ch, n);
    int s = 0;
    for (int i = begin; i < end; i++) s += g_deg[i];
    int lane = tid & 31, w = tid >> 5;
    int v = s;
#pragma unroll
    for (int o = 1; o < 32; o <<= 1) {
        int t = __shfl_up_sync(0xffffffffu, v, o);
        if (lane >= o) v += t;
    }
    if (lane == 31) warp_sums[w] = v;
    __syncthreads();
    if (w == 0) {
        int ws = warp_sums[lane];
#pragma unroll
        for (int o = 1; o < 32; o <<= 1) {
            int t = __shfl_up_sync(0xffffffffu, ws, o);
            if (lane >= o) ws += t;
        }
        warp_sums[lane] = ws;
    }
    __syncthreads();
    int run = v - s + (w ? warp_sums[w - 1] : 0);
    for (int i = begin; i < end; i++) { g_off[i] = run; run += g_deg[i]; }
}

__global__ void scatter_kernel(const int* __restrict__ src, const int* __restrict__ dst, int E)
{
    int e = blockIdx.x * blockDim.x + threadIdx.x;
    if (e < E) {
        int d = dst[e];
        int pos = g_off[d] + atomicAdd(&g_cur[d], 1);
        g_srcs[pos] = src[e];
    }
}

// ---------------- attention: one block per node, one warp per head ----------------
__global__ __launch_bounds__(128) void attn_kernel(int n_nodes)
{
    int n = blockIdx.x;
    if (n >= n_nodes) return;
    int h    = threadIdx.x >> 5;
    int lane = threadIdx.x & 31;

    __shared__ float sc[4][SC_CAP];

    int deg = g_deg[n];
    int off = g_off[n];

    const float* qrow = g_qkvs + (size_t)n * QKVS_W + h * 64;
    float q0 = qrow[lane];
    float q1 = qrow[lane + 32];

    float m = -INFINITY;
    for (int j = 0; j < deg; j++) {
        int src = g_srcs[off + j];
        const float* kr = g_qkvs + (size_t)src * QKVS_W + 256 + h * 64;
        float p = q0 * kr[lane] + q1 * kr[lane + 32];
#pragma unroll
        for (int o = 16; o; o >>= 1) p += __shfl_xor_sync(0xffffffffu, p, o);
        p *= 0.125f;
        if (lane == 0 && j < SC_CAP) sc[h][j] = p;
        m = fmaxf(m, p);
    }
    __syncwarp();

    float s = 0.f, a0 = 0.f, a1 = 0.f;
    for (int j = 0; j < deg; j++) {
        int src = g_srcs[off + j];
        float p;
        if (j < SC_CAP) {
            p = sc[h][j];
        } else {
            const float* kr = g_qkvs + (size_t)src * QKVS_W + 256 + h * 64;
            float pp = q0 * kr[lane] + q1 * kr[lane + 32];
#pragma unroll
            for (int o = 16; o; o >>= 1) pp += __shfl_xor_sync(0xffffffffu, pp, o);
            p = pp * 0.125f;
        }
        float e = expf(p - m);
        const float* vr = g_qkvs + (size_t)src * QKVS_W + 512 + h * 64;
        a0 += e * vr[lane];
        a1 += e * vr[lane + 32];
        s += e;
    }

    float inv = 1.f / (s + 1e-16f);
    const float* sr = g_qkvs + (size_t)n * QKVS_W + 768 + h * 64;
    float o0 = a0 * inv + sr[lane];
    float o1 = a1 * inv + sr[lane + 32];

    // write augmented output [hi|lo|hi] for the second GEMM
    bf16* base = g_maug + (size_t)n * KAUG;
    int c0 = h * 64 + lane, c1 = c0 + 32;
    bf16 h0, l0, h1, l1;
    split_bf16(o0, h0, l0);
    split_bf16(o1, h1, l1);
    base[c0] = h0;       base[c1] = h1;
    base[256 + c0] = l0; base[256 + c1] = l1;
    base[512 + c0] = h0; base[512 + c1] = h1;
}

// ---------------- residual + LayerNorm ----------------
__global__ __launch_bounds__(256) void ln_kernel(const float* __restrict__ x,
                                                 const float* __restrict__ gamma,
                                                 const float* __restrict__ beta,
                                                 float* __restrict__ out, int n_nodes)
{
    int row  = blockIdx.x * 8 + (threadIdx.x >> 5);
    int lane = threadIdx.x & 31;
    if (row >= n_nodes) return;

    const float* t  = g_tmp + (size_t)row * 256;
    const float* xr = x + (size_t)row * 256;

    float h[8];
    float s = 0.f, s2 = 0.f;
#pragma unroll
    for (int i = 0; i < 8; i++) {
        int c = lane + 32 * i;
        h[i] = t[c] + xr[c];
        s  += h[i];
        s2 += h[i] * h[i];
    }
#pragma unroll
    for (int o = 16; o; o >>= 1) {
        s  += __shfl_xor_sync(0xffffffffu, s,  o);
        s2 += __shfl_xor_sync(0xffffffffu, s2, o);
    }
    float mu  = s * (1.f / 256.f);
    float var = s2 * (1.f / 256.f) - mu * mu;
    float r   = rsqrtf(var + 1e-5f);
#pragma unroll
    for (int i = 0; i < 8; i++) {
        int c = lane + 32 * i;
        out[(size_t)row * 256 + c] = (h[i] - mu) * r * gamma[c] + beta[c];
    }
}

// ---------------- launch ----------------
extern "C" void kernel_launch(void* const* d_in, const int* in_sizes, int n_in,
                              void* d_out, int out_size)
{
    const float* x     = (const float*)d_in[0];
    const int*   ei    = (const int*)d_in[1];
    const float* Wq    = (const float*)d_in[2];
    const float* bq    = (const float*)d_in[3];
    const float* Wk    = (const float*)d_in[4];
    const float* bk    = (const float*)d_in[5];
    const float* Wv    = (const float*)d_in[6];
    const float* bv    = (const float*)d_in[7];
    const float* Wsk   = (const float*)d_in[8];
    const float* bsk   = (const float*)d_in[9];
    const float* Wout  = (const float*)d_in[10];
    const float* bout  = (const float*)d_in[11];
    const float* ln_g  = (const float*)d_in[12];
    const float* ln_b  = (const float*)d_in[13];
    float* out = (float*)d_out;

    int N = in_sizes[0] / D_IN;
    int E = in_sizes[1] / 2;

    void* p;
    cudaGetSymbolAddress(&p, g_Waug1); bf16* Waug1 = (bf16*)p;
    cudaGetSymbolAddress(&p, g_Waug2); bf16* Waug2 = (bf16*)p;
    cudaGetSymbolAddress(&p, g_bcat);  float* bcat = (float*)p;
    cudaGetSymbolAddress(&p, g_xaug);  bf16* xaug  = (bf16*)p;
    cudaGetSymbolAddress(&p, g_qkvs);  float* qkvs = (float*)p;
    cudaGetSymbolAddress(&p, g_maug);  bf16* maug  = (bf16*)p;
    cudaGetSymbolAddress(&p, g_tmp);   float* tmp  = (float*)p;

    const int* srcs = ei;
    const int* dsts = ei + E;

    // 1. pack augmented weights + zero counters
    prep_w_kernel<<<(D_IN * QKVS_W + 255) / 256, 256>>>(Wq, Wk, Wv, Wsk, bq, bk, bv, bsk, Wout);
    // 2. convert x to augmented bf16
    conv_x_kernel<<<(N * 128 + 255) / 256, 256>>>(x, N);

    // 3. QKVS projection: [N,768]aug x [768,1024]
    {
        dim3 grid(QKVS_W / 128, (N + 127) / 128);
        mma_gemm<<<grid, 256>>>(xaug, Waug1, bcat, qkvs, N, QKVS_W);
    }

    // 4. CSR build
    hist_kernel<<<(E + 255) / 256, 256>>>(dsts, E);
    scan_kernel<<<1, 1024>>>(N);
    scatter_kernel<<<(E + 255) / 256, 256>>>(srcs, dsts, E);

    // 5. per-node softmax attention + skip (writes augmented bf16)
    attn_kernel<<<N, 128>>>(N);

    // 6. output GEMM: [N,768]aug x [768,256]
    {
        dim3 grid(256 / 128, (N + 127) / 128);
        mma_gemm<<<grid, 256>>>(maug, Waug2, bout, tmp, N, 256);
    }

    // 7. residual + LayerNorm
    ln_kernel<<<(N + 7) / 8, 256>>>(x, ln_g, ln_b, out, N);
}

// round 4
// speedup vs baseline: 1.8741x; 1.1841x over previous
#include <cuda_runtime.h>
#include <cuda_bf16.h>
#include <math.h>
#include <stdint.h>

#define N_NODES 50000
#define N_EDGES 800000
#define D_IN    256
#define QKVS_W  1024
#define KAUG    768

typedef __nv_bfloat16 bf16;

// ---------------- scratch (device globals) ----------------
__device__ bf16  g_Waug1[KAUG * QKVS_W];               // augmented QKVS weights [768,1024]
__device__ bf16  g_Waug2[KAUG * 256];                  // augmented Wout [768,256]
__device__ float g_bcat[QKVS_W];
__device__ bf16  g_xaug[(size_t)N_NODES * KAUG];       // augmented x [N,768] = [hi|lo|hi]
__device__ float g_qkvs[(size_t)N_NODES * QKVS_W];     // Q|K|V|Skip per node (fp32)
__device__ bf16  g_maug[(size_t)N_NODES * KAUG];       // augmented attention output
__device__ float g_tmp[(size_t)N_NODES * 256];         // pre-LN output GEMM result
__device__ int   g_deg[N_NODES];
__device__ int   g_off[N_NODES];
__device__ int   g_cur[N_NODES];
__device__ int   g_srcs[N_EDGES];

__device__ __forceinline__ void split_bf16(float v, bf16& hi, bf16& lo) {
    hi = __float2bfloat16(v);
    lo = __float2bfloat16(v - __bfloat162float(hi));
}

// ---------------- prep: pack augmented weights, zero counters ----------------
__global__ void prep_w_kernel(const float* __restrict__ Wq, const float* __restrict__ Wk,
                              const float* __restrict__ Wv, const float* __restrict__ Ws,
                              const float* __restrict__ bq, const float* __restrict__ bk,
                              const float* __restrict__ bv, const float* __restrict__ bs,
                              const float* __restrict__ Wout)
{
    int idx = blockIdx.x * blockDim.x + threadIdx.x;
    if (idx < D_IN * QKVS_W) {
        int d  = idx >> 10;          // 0..255 (input dim)
        int o  = idx & 1023;         // 0..1023 (output col)
        int sec = o >> 8;
        int oo  = o & 255;
        int h   = oo >> 6;
        int kk  = oo & 63;
        const float* W = (sec == 0) ? Wq : (sec == 1) ? Wk : (sec == 2) ? Wv : Ws;
        float w = W[((h << 8) + d) * 64 + kk];
        bf16 hi, lo; split_bf16(w, hi, lo);
        g_Waug1[(size_t)d * QKVS_W + o] = hi;          // rows [0,256): hi
        g_Waug1[(size_t)(d + 256) * QKVS_W + o] = hi;  // rows [256,512): hi (pairs with A-lo)
        g_Waug1[(size_t)(d + 512) * QKVS_W + o] = lo;  // rows [512,768): lo (pairs with A-hi)
    }
    if (idx < 256 * 256) {
        int d = idx >> 8, o = idx & 255;
        float w = Wout[d * 256 + o];
        bf16 hi, lo; split_bf16(w, hi, lo);
        g_Waug2[(size_t)d * 256 + o] = hi;
        g_Waug2[(size_t)(d + 256) * 256 + o] = hi;
        g_Waug2[(size_t)(d + 512) * 256 + o] = lo;
    }
    if (idx < QKVS_W) {
        int sec = idx >> 8, oo = idx & 255;
        const float* b = (sec == 0) ? bq : (sec == 1) ? bk : (sec == 2) ? bv : bs;
        g_bcat[idx] = b[oo];
    }
    if (idx < N_NODES) { g_deg[idx] = 0; g_cur[idx] = 0; }
}

// x [N,256] fp32 -> xaug [N,768] bf16 ([hi|lo|hi])
__global__ void conv_x_kernel(const float* __restrict__ x, int n_nodes)
{
    int idx = blockIdx.x * blockDim.x + threadIdx.x;   // over N*128 float2s
    if (idx >= n_nodes * 128) return;
    int n = idx >> 7;
    int c = (idx & 127) * 2;
    float2 v = *(const float2*)&x[(size_t)n * 256 + c];
    bf16 h0, l0, h1, l1;
    split_bf16(v.x, h0, l0);
    split_bf16(v.y, h1, l1);
    __nv_bfloat162 hp; hp.x = h0; hp.y = h1;
    __nv_bfloat162 lp; lp.x = l0; lp.y = l1;
    bf16* base = g_xaug + (size_t)n * KAUG;
    *(__nv_bfloat162*)(base + c)       = hp;
    *(__nv_bfloat162*)(base + 256 + c) = lp;
    *(__nv_bfloat162*)(base + 512 + c) = hp;
}

// ---------------- tensor-core GEMM: C[M,Nc] = Aaug[M,768] * Baug[768,Nc] + bias --------
#define ASTRIDE 40
#define BSTRIDE 136

__device__ __forceinline__ void cp16(uint32_t s, const void* g) {
    asm volatile("cp.async.cg.shared.global [%0], [%1], 16;\n" :: "r"(s), "l"(g));
}
__device__ __forceinline__ uint32_t s2u(const void* p) {
    return (uint32_t)__cvta_generic_to_shared(p);
}

__global__ __launch_bounds__(256) void mma_gemm(
    const bf16* __restrict__ A, const bf16* __restrict__ B,
    const float* __restrict__ bias, float* __restrict__ C,
    int M, int Nc)
{
    __shared__ bf16 As[2][128][ASTRIDE];
    __shared__ bf16 Bs[2][32][BSTRIDE];

    int tid  = threadIdx.x;
    int warp = tid >> 5, lane = tid & 31;
    int wm = (warp >> 2) * 64;
    int wn = (warp & 3) * 32;
    int row0 = blockIdx.y * 128;
    int col0 = blockIdx.x * 128;

    float acc[4][4][4];
#pragma unroll
    for (int i = 0; i < 4; i++)
#pragma unroll
        for (int j = 0; j < 4; j++)
#pragma unroll
            for (int k = 0; k < 4; k++) acc[i][j][k] = 0.f;

    int ar = tid >> 2, aq = tid & 3;
    int br = tid >> 4, bq = tid & 15;

    const int NT = KAUG / 32;   // 24

    {
        int k0 = 0, buf = 0;
        int g0 = min(row0 + ar, M - 1), g1 = min(row0 + 64 + ar, M - 1);
        cp16(s2u(&As[buf][ar][aq * 8]),      A + (size_t)g0 * KAUG + k0 + aq * 8);
        cp16(s2u(&As[buf][64 + ar][aq * 8]), A + (size_t)g1 * KAUG + k0 + aq * 8);
        cp16(s2u(&Bs[buf][br][bq * 8]),      B + (size_t)(k0 + br) * Nc + col0 + bq * 8);
        cp16(s2u(&Bs[buf][16 + br][bq * 8]), B + (size_t)(k0 + 16 + br) * Nc + col0 + bq * 8);
        asm volatile("cp.async.commit_group;\n");
    }

    for (int t = 0; t < NT; t++) {
        int buf = t & 1;
        if (t + 1 < NT) {
            int k0 = (t + 1) * 32, nb = (t + 1) & 1;
            int g0 = min(row0 + ar, M - 1), g1 = min(row0 + 64 + ar, M - 1);
            cp16(s2u(&As[nb][ar][aq * 8]),      A + (size_t)g0 * KAUG + k0 + aq * 8);
            cp16(s2u(&As[nb][64 + ar][aq * 8]), A + (size_t)g1 * KAUG + k0 + aq * 8);
            cp16(s2u(&Bs[nb][br][bq * 8]),      B + (size_t)(k0 + br) * Nc + col0 + bq * 8);
            cp16(s2u(&Bs[nb][16 + br][bq * 8]), B + (size_t)(k0 + 16 + br) * Nc + col0 + bq * 8);
            asm volatile("cp.async.commit_group;\n");
            asm volatile("cp.async.wait_group 1;\n");
        } else {
            asm volatile("cp.async.wait_group 0;\n");
        }
        __syncthreads();

#pragma unroll
        for (int kk = 0; kk < 32; kk += 16) {
            uint32_t af[4][4];
#pragma unroll
            for (int mt = 0; mt < 4; mt++) {
                uint32_t addr = s2u(&As[buf][wm + mt * 16 + (lane & 15)][kk + (lane >> 4) * 8]);
                asm volatile("ldmatrix.sync.aligned.m8n8.x4.shared.b16 {%0,%1,%2,%3}, [%4];"
                             : "=r"(af[mt][0]), "=r"(af[mt][1]), "=r"(af[mt][2]), "=r"(af[mt][3])
                             : "r"(addr));
            }
            uint32_t bfr[4][2];
#pragma unroll
            for (int nt = 0; nt < 4; nt++) {
                uint32_t addr = s2u(&Bs[buf][kk + (lane & 15)][wn + nt * 8]);
                asm volatile("ldmatrix.sync.aligned.m8n8.x2.trans.shared.b16 {%0,%1}, [%2];"
                             : "=r"(bfr[nt][0]), "=r"(bfr[nt][1]) : "r"(addr));
            }
#pragma unroll
            for (int mt = 0; mt < 4; mt++)
#pragma unroll
                for (int nt = 0; nt < 4; nt++) {
                    asm volatile(
                        "mma.sync.aligned.m16n8k16.row.col.f32.bf16.bf16.f32 "
                        "{%0,%1,%2,%3}, {%4,%5,%6,%7}, {%8,%9}, {%0,%1,%2,%3};"
                        : "+f"(acc[mt][nt][0]), "+f"(acc[mt][nt][1]),
                          "+f"(acc[mt][nt][2]), "+f"(acc[mt][nt][3])
                        : "r"(af[mt][0]), "r"(af[mt][1]), "r"(af[mt][2]), "r"(af[mt][3]),
                          "r"(bfr[nt][0]), "r"(bfr[nt][1]));
                }
        }
        __syncthreads();
    }

#pragma unroll
    for (int mt = 0; mt < 4; mt++) {
#pragma unroll
        for (int nt = 0; nt < 4; nt++) {
            int c = col0 + wn + nt * 8 + 2 * (lane & 3);
            float2 b2 = *(const float2*)&bias[c];
            int r0 = row0 + wm + mt * 16 + (lane >> 2);
            if (r0 < M) {
                float2 o; o.x = acc[mt][nt][0] + b2.x; o.y = acc[mt][nt][1] + b2.y;
                *(float2*)&C[(size_t)r0 * Nc + c] = o;
            }
            int r1 = r0 + 8;
            if (r1 < M) {
                float2 o; o.x = acc[mt][nt][2] + b2.x; o.y = acc[mt][nt][3] + b2.y;
                *(float2*)&C[(size_t)r1 * Nc + c] = o;
            }
        }
    }
}

// ---------------- CSR build ----------------
__global__ void hist_kernel(const int* __restrict__ dst, int E)
{
    int e = blockIdx.x * blockDim.x + threadIdx.x;
    if (e < E) atomicAdd(&g_deg[dst[e]], 1);
}

__global__ void scan_kernel(int n)
{
    __shared__ int warp_sums[32];
    int tid = threadIdx.x;
    int ch  = (n + 1023) / 1024;
    int begin = tid * ch, end = min(begin + ch, n);
    int s = 0;
    for (int i = begin; i < end; i++) s += g_deg[i];
    int lane = tid & 31, w = tid >> 5;
    int v = s;
#pragma unroll
    for (int o = 1; o < 32; o <<= 1) {
        int t = __shfl_up_sync(0xffffffffu, v, o);
        if (lane >= o) v += t;
    }
    if (lane == 31) warp_sums[w] = v;
    __syncthreads();
    if (w == 0) {
        int ws = warp_sums[lane];
#pragma unroll
        for (int o = 1; o < 32; o <<= 1) {
            int t = __shfl_up_sync(0xffffffffu, ws, o);
            if (lane >= o) ws += t;
        }
        warp_sums[lane] = ws;
    }
    __syncthreads();
    int run = v - s + (w ? warp_sums[w - 1] : 0);
    for (int i = begin; i < end; i++) { g_off[i] = run; run += g_deg[i]; }
}

__global__ void scatter_kernel(const int* __restrict__ src, const int* __restrict__ dst, int E)
{
    int e = blockIdx.x * blockDim.x + threadIdx.x;
    if (e < E) {
        int d = dst[e];
        int pos = g_off[d] + atomicAdd(&g_cur[d], 1);
        g_srcs[pos] = src[e];
    }
}

// ---------------- attention: single-pass online softmax ----------------
// one block per node, one warp per head; 32-wide coalesced src fetch; 2-edge unroll
__global__ __launch_bounds__(128) void attn_kernel(int n_nodes)
{
    int n = blockIdx.x;
    int h    = threadIdx.x >> 5;
    int lane = threadIdx.x & 31;

    int deg = g_deg[n];
    int off = g_off[n];

    const float* qrow = g_qkvs + (size_t)n * QKVS_W + h * 64;
    float q0 = qrow[lane];
    float q1 = qrow[lane + 32];

    float m = -INFINITY, s = 0.f, a0 = 0.f, a1 = 0.f;
    const unsigned FULL = 0xffffffffu;
    const size_t KOFF = 256, VOFF = 512;

    for (int base = 0; base < deg; base += 32) {
        int cnt = min(32, deg - base);
        // coalesced fetch of up to 32 src indices into lane registers
        int my = (lane < cnt) ? g_srcs[off + base + lane] : 0;

        int j = 0;
        for (; j + 1 < cnt; j += 2) {
            int sa = __shfl_sync(FULL, my, j);
            int sb = __shfl_sync(FULL, my, j + 1);
            const float* pa_ = g_qkvs + (size_t)sa * QKVS_W + h * 64;
            const float* pb_ = g_qkvs + (size_t)sb * QKVS_W + h * 64;
            // issue all 8 loads up front (2 edges x K0,K1,V0,V1)
            float ka0 = pa_[KOFF + lane],      kb0 = pb_[KOFF + lane];
            float ka1 = pa_[KOFF + lane + 32], kb1 = pb_[KOFF + lane + 32];
            float va0 = pa_[VOFF + lane],      vb0 = pb_[VOFF + lane];
            float va1 = pa_[VOFF + lane + 32], vb1 = pb_[VOFF + lane + 32];

            float pa = q0 * ka0 + q1 * ka1;
            float pb = q0 * kb0 + q1 * kb1;
#pragma unroll
            for (int o = 16; o; o >>= 1) {
                pa += __shfl_xor_sync(FULL, pa, o);
                pb += __shfl_xor_sync(FULL, pb, o);
            }
            pa *= 0.125f; pb *= 0.125f;

            float nm = fmaxf(m, fmaxf(pa, pb));
            float c  = __expf(m - nm);
            float ea = __expf(pa - nm);
            float eb = __expf(pb - nm);
            s  = s  * c + ea + eb;
            a0 = a0 * c + ea * va0 + eb * vb0;
            a1 = a1 * c + ea * va1 + eb * vb1;
            m = nm;
        }
        if (j < cnt) {
            int sa = __shfl_sync(FULL, my, j);
            const float* pa_ = g_qkvs + (size_t)sa * QKVS_W + h * 64;
            float ka0 = pa_[KOFF + lane];
            float ka1 = pa_[KOFF + lane + 32];
            float va0 = pa_[VOFF + lane];
            float va1 = pa_[VOFF + lane + 32];
            float pa = q0 * ka0 + q1 * ka1;
#pragma unroll
            for (int o = 16; o; o >>= 1) pa += __shfl_xor_sync(FULL, pa, o);
            pa *= 0.125f;
            float nm = fmaxf(m, pa);
            float c  = __expf(m - nm);
            float ea = __expf(pa - nm);
            s  = s  * c + ea;
            a0 = a0 * c + ea * va0;
            a1 = a1 * c + ea * va1;
            m = nm;
        }
    }

    float inv = 1.f / (s + 1e-16f);
    const float* sr = g_qkvs + (size_t)n * QKVS_W + 768 + h * 64;
    float o0 = a0 * inv + sr[lane];
    float o1 = a1 * inv + sr[lane + 32];

    // write augmented output [hi|lo|hi] for the second GEMM
    bf16* baseo = g_maug + (size_t)n * KAUG;
    int c0 = h * 64 + lane, c1 = c0 + 32;
    bf16 h0, l0, h1, l1;
    split_bf16(o0, h0, l0);
    split_bf16(o1, h1, l1);
    baseo[c0] = h0;       baseo[c1] = h1;
    baseo[256 + c0] = l0; baseo[256 + c1] = l1;
    baseo[512 + c0] = h0; baseo[512 + c1] = h1;
}

// ---------------- residual + LayerNorm ----------------
__global__ __launch_bounds__(256) void ln_kernel(const float* __restrict__ x,
                                                 const float* __restrict__ gamma,
                                                 const float* __restrict__ beta,
                                                 float* __restrict__ out, int n_nodes)
{
    int row  = blockIdx.x * 8 + (threadIdx.x >> 5);
    int lane = threadIdx.x & 31;
    if (row >= n_nodes) return;

    const float* t  = g_tmp + (size_t)row * 256;
    const float* xr = x + (size_t)row * 256;

    float h[8];
    float s = 0.f, s2 = 0.f;
#pragma unroll
    for (int i = 0; i < 8; i++) {
        int c = lane + 32 * i;
        h[i] = t[c] + xr[c];
        s  += h[i];
        s2 += h[i] * h[i];
    }
#pragma unroll
    for (int o = 16; o; o >>= 1) {
        s  += __shfl_xor_sync(0xffffffffu, s,  o);
        s2 += __shfl_xor_sync(0xffffffffu, s2, o);
    }
    float mu  = s * (1.f / 256.f);
    float var = s2 * (1.f / 256.f) - mu * mu;
    float r   = rsqrtf(var + 1e-5f);
#pragma unroll
    for (int i = 0; i < 8; i++) {
        int c = lane + 32 * i;
        out[(size_t)row * 256 + c] = (h[i] - mu) * r * gamma[c] + beta[c];
    }
}

// ---------------- launch ----------------
extern "C" void kernel_launch(void* const* d_in, const int* in_sizes, int n_in,
                              void* d_out, int out_size)
{
    const float* x     = (const float*)d_in[0];
    const int*   ei    = (const int*)d_in[1];
    const float* Wq    = (const float*)d_in[2];
    const float* bq    = (const float*)d_in[3];
    const float* Wk    = (const float*)d_in[4];
    const float* bk    = (const float*)d_in[5];
    const float* Wv    = (const float*)d_in[6];
    const float* bv    = (const float*)d_in[7];
    const float* Wsk   = (const float*)d_in[8];
    const float* bsk   = (const float*)d_in[9];
    const float* Wout  = (const float*)d_in[10];
    const float* bout  = (const float*)d_in[11];
    const float* ln_g  = (const float*)d_in[12];
    const float* ln_b  = (const float*)d_in[13];
    float* out = (float*)d_out;

    int N = in_sizes[0] / D_IN;
    int E = in_sizes[1] / 2;

    void* p;
    cudaGetSymbolAddress(&p, g_Waug1); bf16* Waug1 = (bf16*)p;
    cudaGetSymbolAddress(&p, g_Waug2); bf16* Waug2 = (bf16*)p;
    cudaGetSymbolAddress(&p, g_bcat);  float* bcat = (float*)p;
    cudaGetSymbolAddress(&p, g_xaug);  bf16* xaug  = (bf16*)p;
    cudaGetSymbolAddress(&p, g_qkvs);  float* qkvs = (float*)p;
    cudaGetSymbolAddress(&p, g_maug);  bf16* maug  = (bf16*)p;
    cudaGetSymbolAddress(&p, g_tmp);   float* tmp  = (float*)p;

    const int* srcs = ei;
    const int* dsts = ei + E;

    prep_w_kernel<<<(D_IN * QKVS_W + 255) / 256, 256>>>(Wq, Wk, Wv, Wsk, bq, bk, bv, bsk, Wout);
    conv_x_kernel<<<(N * 128 + 255) / 256, 256>>>(x, N);

    {
        dim3 grid(QKVS_W / 128, (N + 127) / 128);
        mma_gemm<<<grid, 256>>>(xaug, Waug1, bcat, qkvs, N, QKVS_W);
    }

    hist_kernel<<<(E + 255) / 256, 256>>>(dsts, E);
    scan_kernel<<<1, 1024>>>(N);
    scatter_kernel<<<(E + 255) / 256, 256>>>(srcs, dsts, E);

    attn_kernel<<<N, 128>>>(N);

    {
        dim3 grid(256 / 128, (N + 127) / 128);
        mma_gemm<<<grid, 256>>>(maug, Waug2, bout, tmp, N, 256);
    }

    ln_kernel<<<(N + 7) / 8, 256>>>(x, ln_g, ln_b, out, N);
}